// round 1
// baseline (speedup 1.0000x reference)
#include <cuda_runtime.h>
#include <math.h>

#define NODES 100000
#define GRAPHS 100
#define NPG 1000
#define CH 128
#define OUTD 64
#define POSD 16
#define TM 64
#define WPAD 129
#define APAD 66

// ---- scratch (device globals: no allocation allowed) ----
__device__ float g_y0[(size_t)NODES * CH];
__device__ float g_y1[(size_t)NODES * CH];
__device__ float g_M0[2 * CH];
__device__ float g_beff0[CH];
__device__ float g_sum[2][CH];
__device__ float g_sq[2][CH];
__device__ float g_scale[2][CH];
__device__ float g_shift[2][CH];
__device__ float g_pool[GRAPHS * CH];

__device__ __forceinline__ unsigned long long pack2(float lo, float hi) {
    unsigned long long r;
    asm("mov.b64 %0, {%1,%2};" : "=l"(r) : "f"(lo), "f"(hi));
    return r;
}
__device__ __forceinline__ void unpack2(unsigned long long v, float& lo, float& hi) {
    asm("mov.b64 {%0,%1}, %2;" : "=f"(lo), "=f"(hi) : "l"(v));
}
__device__ __forceinline__ unsigned long long fma2(unsigned long long a, unsigned long long b,
                                                   unsigned long long c) {
    unsigned long long d;
    asm("fma.rn.f32x2 %0, %1, %2, %3;" : "=l"(d) : "l"(a), "l"(b), "l"(c));
    return d;
}

// K0: zero accumulators + fold positional encoding into (M0, beff0)
__global__ void k_prep(const float* __restrict__ peW, const float* __restrict__ peB,
                       const float* __restrict__ W0, const float* __restrict__ bias0) {
    int t = blockIdx.x * blockDim.x + threadIdx.x;
    int stride = gridDim.x * blockDim.x;
    for (int i = t; i < GRAPHS * CH; i += stride) g_pool[i] = 0.f;
    for (int i = t; i < CH; i += stride) {
        g_sum[0][i] = 0.f; g_sum[1][i] = 0.f;
        g_sq[0][i] = 0.f;  g_sq[1][i] = 0.f;
    }
    if (blockIdx.x == 0 && threadIdx.x < CH) {
        int c = threadIdx.x;
        float m0 = 0.f, m1 = 0.f, be = 0.f;
        for (int k = 0; k < POSD; k++) {
            float w = W0[c * 144 + 128 + k];
            m0 += peW[2 * k] * w;
            m1 += peW[2 * k + 1] * w;
            be += peB[k] * w;
        }
        g_M0[c] = m0; g_M0[CH + c] = m1;
        g_beff0[c] = be + bias0[c];
    }
}

// Fused GEMM: y = in @ W.T + bias (+ pos terms for layer0) with BN-stat accumulation.
// layer==0: in = x (global), epilogue adds pos @ M0 + beff0, out -> g_y0
// layer==1: in = elu(bn0(g_y0)) applied on load, bias = bias1, out -> g_y1
__global__ __launch_bounds__(256, 2) void k_gemm(const float* __restrict__ x,
                                                 const float* __restrict__ W,
                                                 const float* __restrict__ bias1,
                                                 int layer) {
    extern __shared__ float smem[];
    float* Ws  = smem;                 // [CH][WPAD]
    float* As  = Ws + CH * WPAD;       // [CH][APAD]  (k-major, node contiguous)
    float* Px  = As + CH * APAD;       // [TM]
    float* Py  = Px + TM;              // [TM]
    float* M0s = Py + TM;              // [2*CH]
    float* Bs  = M0s + 2 * CH;         // [CH]

    int tid = threadIdx.x;
    int nb = blockIdx.x * TM;
    int wstride = (layer == 0) ? 144 : CH;

    for (int i = tid; i < CH * CH; i += 256) {
        int c = i >> 7, k = i & 127;
        Ws[c * WPAD + k] = W[c * wstride + k];
    }
    if (layer == 0) {
        for (int i = tid; i < 2 * CH; i += 256) M0s[i] = g_M0[i];
        for (int i = tid; i < CH; i += 256) Bs[i] = g_beff0[i];
        for (int i = tid; i < TM; i += 256) {
            int local = (nb + i) % NPG;
            Px[i] = (float)(local >> 5) * (1.f / 31.f);
            Py[i] = (float)(local & 31) * (1.f / 31.f);
        }
        for (int i = tid; i < TM * CH; i += 256) {
            int n = i >> 7, k = i & 127;
            int gn = nb + n;
            float v = (gn < NODES) ? x[(size_t)gn * CH + k] : 0.f;
            As[k * APAD + n] = v;
        }
    } else {
        for (int i = tid; i < CH; i += 256) Bs[i] = bias1[i];
        for (int i = tid; i < TM * CH; i += 256) {
            int n = i >> 7, k = i & 127;
            int gn = nb + n;
            float v = (gn < NODES) ? g_y0[(size_t)gn * CH + k] : 0.f;
            v = v * g_scale[0][k] + g_shift[0][k];
            v = (v > 0.f) ? v : (expf(v) - 1.f);
            As[k * APAD + n] = v;
        }
    }
    __syncthreads();

    int lane = tid & 31;
    int n0 = (tid >> 5) * 8;              // 8 nodes per thread (4 f32x2 pairs)
    unsigned long long acc[4][4];
#pragma unroll
    for (int p = 0; p < 4; p++)
#pragma unroll
        for (int j = 0; j < 4; j++) acc[p][j] = 0ULL;

#pragma unroll 4
    for (int k = 0; k < CH; k++) {
        unsigned long long a2[4];
#pragma unroll
        for (int p = 0; p < 4; p++) {
            float2 t = *(const float2*)&As[k * APAD + n0 + 2 * p];
            a2[p] = pack2(t.x, t.y);
        }
#pragma unroll
        for (int j = 0; j < 4; j++) {
            float b = Ws[(lane + 32 * j) * WPAD + k];
            unsigned long long b2 = pack2(b, b);
#pragma unroll
            for (int p = 0; p < 4; p++) acc[p][j] = fma2(a2[p], b2, acc[p][j]);
        }
    }

    // epilogue: bias (+pos), store, per-block BN stat partials
    float psum[4] = {0, 0, 0, 0}, psq[4] = {0, 0, 0, 0};
    float* dst = (layer == 0) ? g_y0 : g_y1;
#pragma unroll
    for (int p = 0; p < 4; p++) {
        int nl0 = n0 + 2 * p, nl1 = nl0 + 1;
        int gn0 = nb + nl0, gn1 = nb + nl1;
#pragma unroll
        for (int j = 0; j < 4; j++) {
            int c = lane + 32 * j;
            float v0, v1;
            unpack2(acc[p][j], v0, v1);
            v0 += Bs[c]; v1 += Bs[c];
            if (layer == 0) {
                v0 += Px[nl0] * M0s[c] + Py[nl0] * M0s[CH + c];
                v1 += Px[nl1] * M0s[c] + Py[nl1] * M0s[CH + c];
            }
            if (gn0 < NODES) dst[(size_t)gn0 * CH + c] = v0; else v0 = 0.f;
            if (gn1 < NODES) dst[(size_t)gn1 * CH + c] = v1; else v1 = 0.f;
            psum[j] += v0 + v1;
            psq[j] += v0 * v0 + v1 * v1;
        }
    }
    __syncthreads();
    float* red = As;  // reuse
#pragma unroll
    for (int j = 0; j < 4; j++) red[(tid >> 5) * CH + lane + 32 * j] = psum[j];
    __syncthreads();
    if (tid < CH) {
        float s = 0.f;
#pragma unroll
        for (int g = 0; g < 8; g++) s += red[g * CH + tid];
        atomicAdd(&g_sum[layer][tid], s);
    }
    __syncthreads();
#pragma unroll
    for (int j = 0; j < 4; j++) red[(tid >> 5) * CH + lane + 32 * j] = psq[j];
    __syncthreads();
    if (tid < CH) {
        float s = 0.f;
#pragma unroll
        for (int g = 0; g < 8; g++) s += red[g * CH + tid];
        atomicAdd(&g_sq[layer][tid], s);
    }
}

__global__ void k_bnfin(const float* __restrict__ gam, const float* __restrict__ bet, int layer) {
    int c = threadIdx.x;
    float mu = g_sum[layer][c] * (1.f / NODES);
    float var = g_sq[layer][c] * (1.f / NODES) - mu * mu;
    float sc = gam[c] * rsqrtf(var + 1e-5f);
    g_scale[layer][c] = sc;
    g_shift[layer][c] = bet[c] - mu * sc;
}

// per-graph mean of elu(bn1(y1)) -> g_pool (sum; divided in k_fc)
__global__ __launch_bounds__(256) void k_pool() {
    int g = blockIdx.x >> 3;
    int sub = blockIdx.x & 7;
    int nstart = g * NPG + sub * 125;
    int c = threadIdx.x & 127;
    int half = threadIdx.x >> 7;
    float sc = g_scale[1][c], sh = g_shift[1][c];
    float s = 0.f;
    for (int n = nstart + half; n < nstart + 125; n += 2) {
        float v = g_y1[(size_t)n * CH + c] * sc + sh;
        v = (v > 0.f) ? v : (expf(v) - 1.f);
        s += v;
    }
    __shared__ float red[256];
    red[threadIdx.x] = s;
    __syncthreads();
    if (half == 0) atomicAdd(&g_pool[g * CH + c], red[c] + red[128 + c]);
}

__global__ void k_fc(const float* __restrict__ fcW, const float* __restrict__ fcb,
                     float* __restrict__ out) {
    int g = blockIdx.x;
    int o = threadIdx.x;  // 64 threads
    float s = 0.f;
#pragma unroll 8
    for (int c = 0; c < CH; c++) s += g_pool[g * CH + c] * fcW[o * CH + c];
    out[g * OUTD + o] = s * (1.f / NPG) + fcb[o];
}

extern "C" void kernel_launch(void* const* d_in, const int* in_sizes, int n_in,
                              void* d_out, int out_size) {
    const float* x   = (const float*)d_in[0];
    // d_in[1] edge_index, d_in[2] batch: provably unused (attention collapses)
    const float* peW = (const float*)d_in[3];
    const float* peB = (const float*)d_in[4];
    const float* W0  = (const float*)d_in[5];
    const float* b0  = (const float*)d_in[8];
    const float* g0  = (const float*)d_in[9];
    const float* bb0 = (const float*)d_in[10];
    const float* W1  = (const float*)d_in[11];
    const float* b1  = (const float*)d_in[14];
    const float* g1  = (const float*)d_in[15];
    const float* bb1 = (const float*)d_in[16];
    const float* fcW = (const float*)d_in[17];
    const float* fcb = (const float*)d_in[18];
    float* out = (float*)d_out;

    const int smem_bytes = (CH * WPAD + CH * APAD + 2 * TM + 2 * CH + CH) * (int)sizeof(float);
    static bool attr_set = false;
    if (!attr_set) {
        cudaFuncSetAttribute(k_gemm, cudaFuncAttributeMaxDynamicSharedMemorySize, smem_bytes);
        attr_set = true;
    }

    int nblk = (NODES + TM - 1) / TM;
    k_prep<<<64, 256>>>(peW, peB, W0, b0);
    k_gemm<<<nblk, 256, smem_bytes>>>(x, W0, b0, 0);
    k_bnfin<<<1, CH>>>(g0, bb0, 0);
    k_gemm<<<nblk, 256, smem_bytes>>>(x, W1, b1, 1);
    k_bnfin<<<1, CH>>>(g1, bb1, 1);
    k_pool<<<GRAPHS * 8, 256>>>();
    k_fc<<<GRAPHS, OUTD>>>(fcW, fcb, out);
}

// round 3
// speedup vs baseline: 1.7167x; 1.7167x over previous
#include <cuda_runtime.h>
#include <cuda_bf16.h>
#include <math.h>
#include <stdint.h>

#define NODES 100000
#define GRAPHS 100
#define NPG 1000
#define CH 128
#define OUTD 64
#define POSD 16
#define TM 64
#define NBLK ((NODES + TM - 1) / TM)
#define DSMEM 98304   // Ahi 16K | Alo 16K | Whi 32K | Wlo 32K

// ---- device-global scratch (no allocation allowed) ----
__device__ float4 g_y0[(size_t)NODES * CH / 4];
__device__ float4 g_y1[(size_t)NODES * CH / 4];
__device__ unsigned char g_Wimg[2][2][32768];  // [layer][hi|lo] pre-swizzled bf16 images
__device__ float g_M0[2 * CH];
__device__ float g_beff0[CH];
__device__ float g_sum[2][CH];
__device__ float g_sq[2][CH];
__device__ float g_scale[2][CH];
__device__ float g_shift[2][CH];
__device__ float g_pool[GRAPHS * CH];

__device__ __forceinline__ uint32_t smem_u32(const void* p) {
    uint32_t a;
    asm("{ .reg .u64 t; cvta.to.shared.u64 t, %1; cvt.u32.u64 %0, t; }" : "=r"(a) : "l"(p));
    return a;
}
// swizzled byte offset inside a [rows][128] bf16 tile image (256B rows, 16B chunks)
__device__ __forceinline__ uint32_t swz(uint32_t row, uint32_t chunk) {
    return row * 256u + ((chunk ^ (row & 7u)) << 4);
}
__device__ __forceinline__ void ldsm4(uint32_t& r0, uint32_t& r1, uint32_t& r2, uint32_t& r3,
                                      uint32_t addr) {
    asm volatile("ldmatrix.sync.aligned.m8n8.x4.shared.b16 {%0,%1,%2,%3}, [%4];"
                 : "=r"(r0), "=r"(r1), "=r"(r2), "=r"(r3) : "r"(addr));
}
__device__ __forceinline__ void mma_bf16(float* c, uint32_t a0, uint32_t a1, uint32_t a2,
                                         uint32_t a3, uint32_t b0, uint32_t b1) {
    asm volatile(
        "mma.sync.aligned.m16n8k16.row.col.f32.bf16.bf16.f32 "
        "{%0,%1,%2,%3}, {%4,%5,%6,%7}, {%8,%9}, {%0,%1,%2,%3};"
        : "+f"(c[0]), "+f"(c[1]), "+f"(c[2]), "+f"(c[3])
        : "r"(a0), "r"(a1), "r"(a2), "r"(a3), "r"(b0), "r"(b1));
}
__device__ __forceinline__ uint32_t split_pack_hi(float v0, float v1, uint32_t& lo) {
    __nv_bfloat16 h0 = __float2bfloat16(v0), h1 = __float2bfloat16(v1);
    __nv_bfloat16 l0 = __float2bfloat16(v0 - __bfloat162float(h0));
    __nv_bfloat16 l1 = __float2bfloat16(v1 - __bfloat162float(h1));
    lo = (uint32_t)__bfloat16_as_ushort(l0) | ((uint32_t)__bfloat16_as_ushort(l1) << 16);
    return (uint32_t)__bfloat16_as_ushort(h0) | ((uint32_t)__bfloat16_as_ushort(h1) << 16);
}

// ---- prep: zero accumulators, fold PE into (M0,beff0), build swizzled bf16 W images ----
__global__ void k_prep(const float* __restrict__ peW, const float* __restrict__ peB,
                       const float* __restrict__ W0, const float* __restrict__ b0,
                       const float* __restrict__ W1) {
    int t = blockIdx.x * blockDim.x + threadIdx.x;
    int stride = gridDim.x * blockDim.x;
    for (int i = t; i < GRAPHS * CH; i += stride) g_pool[i] = 0.f;
    for (int i = t; i < CH; i += stride) {
        g_sum[0][i] = 0.f; g_sum[1][i] = 0.f;
        g_sq[0][i] = 0.f;  g_sq[1][i] = 0.f;
    }
    for (int i = t; i < 2 * CH * CH; i += stride) {
        int layer = i >> 14, e = i & 16383, c = e >> 7, k = e & 127;
        float w = layer ? W1[c * CH + k] : W0[c * 144 + k];
        __nv_bfloat16 h = __float2bfloat16(w);
        __nv_bfloat16 l = __float2bfloat16(w - __bfloat162float(h));
        uint32_t off = swz((uint32_t)c, (uint32_t)(k >> 3)) + (k & 7) * 2;
        *(__nv_bfloat16*)(g_Wimg[layer][0] + off) = h;
        *(__nv_bfloat16*)(g_Wimg[layer][1] + off) = l;
    }
    if (blockIdx.x == 0 && threadIdx.x < CH) {
        int c = threadIdx.x;
        float m0 = 0.f, m1 = 0.f, be = 0.f;
        for (int k = 0; k < POSD; k++) {
            float w = W0[c * 144 + 128 + k];
            m0 += peW[2 * k] * w;
            m1 += peW[2 * k + 1] * w;
            be += peB[k] * w;
        }
        g_M0[c] = m0; g_M0[CH + c] = m1;
        g_beff0[c] = be + b0[c];
    }
}

// ---- fused GEMM layer via mma.sync bf16 3-term split ----
__global__ __launch_bounds__(256, 2) void k_gemm(const float* __restrict__ xin,
                                                 const float* __restrict__ bias,
                                                 int layer) {
    extern __shared__ char sm[];
    char* Ahi = sm;              // [64][256B]
    char* Alo = sm + 16384;
    char* Whi = sm + 32768;      // [128][256B]
    char* Wlo = sm + 65536;

    __shared__ float s_B[CH], s_M0x[CH], s_M0y[CH], s_sc[CH], s_sh[CH];
    __shared__ float s_Px[TM], s_Py[TM];

    int tid = threadIdx.x;
    int wid = tid >> 5;
    int lane = tid & 31;
    int nb = blockIdx.x * TM;

    if (tid < CH) {
        s_B[tid] = layer ? bias[tid] : g_beff0[tid];
        s_M0x[tid] = g_M0[tid];
        s_M0y[tid] = g_M0[CH + tid];
        s_sc[tid] = g_scale[0][tid];
        s_sh[tid] = g_shift[0][tid];
    }
    if (tid < TM) {
        int local = (nb + tid) % NPG;
        s_Px[tid] = (float)(local >> 5) * (1.f / 31.f);
        s_Py[tid] = (float)(local & 31) * (1.f / 31.f);
    }
    __syncthreads();

    // ---- load + split A tile: 64 rows x 16 chunks of 8 ch ----
    const float4* src4 = layer ? (const float4*)g_y0 : (const float4*)xin;
#pragma unroll
    for (int i = 0; i < 4; i++) {
        int u = tid + 256 * i;        // 0..1023
        int row = u >> 4;
        int chunk = u & 15;
        int gn = nb + row;
        float v[8];
        if (gn < NODES) {
            float4 p0 = src4[(size_t)gn * 32 + chunk * 2];
            float4 p1 = src4[(size_t)gn * 32 + chunk * 2 + 1];
            v[0] = p0.x; v[1] = p0.y; v[2] = p0.z; v[3] = p0.w;
            v[4] = p1.x; v[5] = p1.y; v[6] = p1.z; v[7] = p1.w;
            if (layer) {
#pragma unroll
                for (int j = 0; j < 8; j++) {
                    int c = chunk * 8 + j;
                    float a = v[j] * s_sc[c] + s_sh[c];
                    v[j] = (a > 0.f) ? a : (expf(a) - 1.f);
                }
            }
        } else {
#pragma unroll
            for (int j = 0; j < 8; j++) v[j] = 0.f;
        }
        uint4 hi, lo;
        hi.x = split_pack_hi(v[0], v[1], lo.x);
        hi.y = split_pack_hi(v[2], v[3], lo.y);
        hi.z = split_pack_hi(v[4], v[5], lo.z);
        hi.w = split_pack_hi(v[6], v[7], lo.w);
        uint32_t off = swz((uint32_t)row, (uint32_t)chunk);
        *(uint4*)(Ahi + off) = hi;
        *(uint4*)(Alo + off) = lo;
    }
    // ---- copy W images (already swizzled) ----
    {
        const float4* wh = (const float4*)g_Wimg[layer][0];
        const float4* wl = (const float4*)g_Wimg[layer][1];
#pragma unroll
        for (int i = 0; i < 8; i++) {
            ((float4*)Whi)[tid + 256 * i] = wh[tid + 256 * i];
            ((float4*)Wlo)[tid + 256 * i] = wl[tid + 256 * i];
        }
    }
    __syncthreads();

    // ---- mma mainloop ----
    int wr = wid >> 1;          // row group 0..3 -> rows 16*wr
    int wc = wid & 1;           // ch half 0..1 -> ch 64*wc
    uint32_t la7 = lane & 7;
    uint32_t aRow = (uint32_t)(16 * wr + (lane & 15)) * 256u;
    uint32_t aSel = (uint32_t)(lane >> 4);
    uint32_t bRow = (uint32_t)(64 * wc + (lane & 7) + ((lane >> 4) << 3)) * 256u;
    uint32_t bSel = (uint32_t)((lane >> 3) & 1);
    uint32_t baseAh = smem_u32(Ahi), baseAl = smem_u32(Alo);
    uint32_t baseWh = smem_u32(Whi), baseWl = smem_u32(Wlo);

    float C[8][4];
#pragma unroll
    for (int n = 0; n < 8; n++)
#pragma unroll
        for (int j = 0; j < 4; j++) C[n][j] = 0.f;

#pragma unroll
    for (int ks = 0; ks < 8; ks++) {
        uint32_t ca = 2 * ks + aSel;
        uint32_t aoff = aRow + ((ca ^ la7) << 4);
        uint32_t ah0, ah1, ah2, ah3, al0, al1, al2, al3;
        ldsm4(ah0, ah1, ah2, ah3, baseAh + aoff);
        ldsm4(al0, al1, al2, al3, baseAl + aoff);
        uint32_t cb = 2 * ks + bSel;
        uint32_t bsw = (cb ^ la7) << 4;
#pragma unroll
        for (int np = 0; np < 4; np++) {
            uint32_t boff = bRow + np * 4096 + bsw;
            uint32_t wh0, wh1, wh2, wh3, wl0, wl1, wl2, wl3;
            ldsm4(wh0, wh1, wh2, wh3, baseWh + boff);
            ldsm4(wl0, wl1, wl2, wl3, baseWl + boff);
            mma_bf16(C[2 * np],     ah0, ah1, ah2, ah3, wh0, wh1);
            mma_bf16(C[2 * np + 1], ah0, ah1, ah2, ah3, wh2, wh3);
            mma_bf16(C[2 * np],     al0, al1, al2, al3, wh0, wh1);
            mma_bf16(C[2 * np + 1], al0, al1, al2, al3, wh2, wh3);
            mma_bf16(C[2 * np],     ah0, ah1, ah2, ah3, wl0, wl1);
            mma_bf16(C[2 * np + 1], ah0, ah1, ah2, ah3, wl2, wl3);
        }
    }
    __syncthreads();

    // ---- stage C to smem ----
    float* stage = (float*)sm;     // [64][132]
    {
        int tr = lane >> 2;
        int tc = (lane & 3) * 2;
        int r0 = 16 * wr + tr, r1 = r0 + 8;
#pragma unroll
        for (int nt = 0; nt < 8; nt++) {
            int c = 64 * wc + 8 * nt + tc;
            *(float2*)&stage[r0 * 132 + c] = make_float2(C[nt][0], C[nt][1]);
            *(float2*)&stage[r1 * 132 + c] = make_float2(C[nt][2], C[nt][3]);
        }
    }
    __syncthreads();

    // ---- writeout + BN stats ----
    {
        int c = tid & 127;
        int half = tid >> 7;
        float bc = s_B[c], mx = s_M0x[c], my = s_M0y[c];
        float* dst = layer ? (float*)g_y1 : (float*)g_y0;
        float s = 0.f, q = 0.f;
#pragma unroll 4
        for (int r = half * 32; r < half * 32 + 32; r++) {
            int node = nb + r;
            if (node < NODES) {
                float v = stage[r * 132 + c] + bc;
                if (!layer) v += s_Px[r] * mx + s_Py[r] * my;
                dst[(size_t)node * CH + c] = v;
                s += v;
                q += v * v;
            }
        }
        atomicAdd(&g_sum[layer][c], s);
        atomicAdd(&g_sq[layer][c], q);
    }
}

__global__ void k_bnfin(const float* __restrict__ gam, const float* __restrict__ bet, int layer) {
    int c = threadIdx.x;
    float mu = g_sum[layer][c] * (1.f / NODES);
    float var = g_sq[layer][c] * (1.f / NODES) - mu * mu;
    float sc = gam[c] * rsqrtf(var + 1e-5f);
    g_scale[layer][c] = sc;
    g_shift[layer][c] = bet[c] - mu * sc;
}

__global__ __launch_bounds__(256) void k_pool() {
    int g = blockIdx.x >> 3;
    int sub = blockIdx.x & 7;
    int nstart = g * NPG + sub * 125;
    int c = threadIdx.x & 127;
    int half = threadIdx.x >> 7;
    const float* y1 = (const float*)g_y1;
    float sc = g_scale[1][c], sh = g_shift[1][c];
    float s = 0.f;
    for (int n = nstart + half; n < nstart + 125; n += 2) {
        float v = y1[(size_t)n * CH + c] * sc + sh;
        v = (v > 0.f) ? v : (expf(v) - 1.f);
        s += v;
    }
    __shared__ float red[256];
    red[threadIdx.x] = s;
    __syncthreads();
    if (half == 0) atomicAdd(&g_pool[g * CH + c], red[c] + red[128 + c]);
}

__global__ void k_fc(const float* __restrict__ fcW, const float* __restrict__ fcb,
                     float* __restrict__ out) {
    int g = blockIdx.x;
    int o = threadIdx.x;
    float s = 0.f;
#pragma unroll 8
    for (int c = 0; c < CH; c++) s += g_pool[g * CH + c] * fcW[o * CH + c];
    out[g * OUTD + o] = s * (1.f / NPG) + fcb[o];
}

extern "C" void kernel_launch(void* const* d_in, const int* in_sizes, int n_in,
                              void* d_out, int out_size) {
    const float* x   = (const float*)d_in[0];
    const float* peW = (const float*)d_in[3];
    const float* peB = (const float*)d_in[4];
    const float* W0  = (const float*)d_in[5];
    const float* b0  = (const float*)d_in[8];
    const float* g0  = (const float*)d_in[9];
    const float* bb0 = (const float*)d_in[10];
    const float* W1  = (const float*)d_in[11];
    const float* b1  = (const float*)d_in[14];
    const float* g1  = (const float*)d_in[15];
    const float* bb1 = (const float*)d_in[16];
    const float* fcW = (const float*)d_in[17];
    const float* fcb = (const float*)d_in[18];
    float* out = (float*)d_out;

    static bool once = false;
    if (!once) {
        cudaFuncSetAttribute(k_gemm, cudaFuncAttributeMaxDynamicSharedMemorySize, DSMEM);
        once = true;
    }

    k_prep<<<128, 256>>>(peW, peB, W0, b0, W1);
    k_gemm<<<NBLK, 256, DSMEM>>>(x, b0, 0);
    k_bnfin<<<1, CH>>>(g0, bb0, 0);
    k_gemm<<<NBLK, 256, DSMEM>>>(x, b1, 1);
    k_bnfin<<<1, CH>>>(g1, bb1, 1);
    k_pool<<<GRAPHS * 8, 256>>>();
    k_fc<<<GRAPHS, OUTD>>>(fcW, fcb, out);
}

// round 4
// speedup vs baseline: 1.8080x; 1.0531x over previous
#include <cuda_runtime.h>
#include <cuda_bf16.h>
#include <math.h>
#include <stdint.h>

#define NODES 100000
#define GRAPHS 100
#define NPG 1000
#define CH 128
#define OUTD 64
#define POSD 16
#define TM 128
#define NBLK ((NODES + TM - 1) / TM)
#define DSMEM 98304   // Ahi 32K | Alo 32K | Wbuf 32K

// ---- device-global scratch ----
__device__ float4 g_y0[(size_t)NODES * CH / 4];
__device__ float4 g_y1[(size_t)NODES * CH / 4];
__device__ unsigned char g_Wimg[2][2][32768];  // [layer][hi|lo] pre-swizzled bf16 images
__device__ float g_M0[2 * CH];
__device__ float g_beff0[CH];
__device__ float g_sum[2][CH];
__device__ float g_sq[2][CH];
__device__ float g_scale[2][CH];
__device__ float g_shift[2][CH];
__device__ float g_pool[GRAPHS * CH];

__device__ __forceinline__ uint32_t smem_u32(const void* p) {
    uint32_t a;
    asm("{ .reg .u64 t; cvta.to.shared.u64 t, %1; cvt.u32.u64 %0, t; }" : "=r"(a) : "l"(p));
    return a;
}
__device__ __forceinline__ uint32_t swz(uint32_t row, uint32_t chunk) {
    return row * 256u + ((chunk ^ (row & 7u)) << 4);
}
__device__ __forceinline__ void ldsm4(uint32_t& r0, uint32_t& r1, uint32_t& r2, uint32_t& r3,
                                      uint32_t addr) {
    asm volatile("ldmatrix.sync.aligned.m8n8.x4.shared.b16 {%0,%1,%2,%3}, [%4];"
                 : "=r"(r0), "=r"(r1), "=r"(r2), "=r"(r3) : "r"(addr));
}
__device__ __forceinline__ void mma_bf16(float* c, uint32_t a0, uint32_t a1, uint32_t a2,
                                         uint32_t a3, uint32_t b0, uint32_t b1) {
    asm volatile(
        "mma.sync.aligned.m16n8k16.row.col.f32.bf16.bf16.f32 "
        "{%0,%1,%2,%3}, {%4,%5,%6,%7}, {%8,%9}, {%0,%1,%2,%3};"
        : "+f"(c[0]), "+f"(c[1]), "+f"(c[2]), "+f"(c[3])
        : "r"(a0), "r"(a1), "r"(a2), "r"(a3), "r"(b0), "r"(b1));
}
__device__ __forceinline__ uint32_t split_pack_hi(float v0, float v1, uint32_t& lo) {
    __nv_bfloat16 h0 = __float2bfloat16(v0), h1 = __float2bfloat16(v1);
    __nv_bfloat16 l0 = __float2bfloat16(v0 - __bfloat162float(h0));
    __nv_bfloat16 l1 = __float2bfloat16(v1 - __bfloat162float(h1));
    lo = (uint32_t)__bfloat16_as_ushort(l0) | ((uint32_t)__bfloat16_as_ushort(l1) << 16);
    return (uint32_t)__bfloat16_as_ushort(h0) | ((uint32_t)__bfloat16_as_ushort(h1) << 16);
}

__global__ void k_prep(const float* __restrict__ peW, const float* __restrict__ peB,
                       const float* __restrict__ W0, const float* __restrict__ b0,
                       const float* __restrict__ W1) {
    int t = blockIdx.x * blockDim.x + threadIdx.x;
    int stride = gridDim.x * blockDim.x;
    for (int i = t; i < GRAPHS * CH; i += stride) g_pool[i] = 0.f;
    for (int i = t; i < CH; i += stride) {
        g_sum[0][i] = 0.f; g_sum[1][i] = 0.f;
        g_sq[0][i] = 0.f;  g_sq[1][i] = 0.f;
    }
    for (int i = t; i < 2 * CH * CH; i += stride) {
        int layer = i >> 14, e = i & 16383, c = e >> 7, k = e & 127;
        float w = layer ? W1[c * CH + k] : W0[c * 144 + k];
        __nv_bfloat16 h = __float2bfloat16(w);
        __nv_bfloat16 l = __float2bfloat16(w - __bfloat162float(h));
        uint32_t off = swz((uint32_t)c, (uint32_t)(k >> 3)) + (k & 7) * 2;
        *(__nv_bfloat16*)(g_Wimg[layer][0] + off) = h;
        *(__nv_bfloat16*)(g_Wimg[layer][1] + off) = l;
    }
    if (blockIdx.x == 0 && threadIdx.x < CH) {
        int c = threadIdx.x;
        float m0 = 0.f, m1 = 0.f, be = 0.f;
        for (int k = 0; k < POSD; k++) {
            float w = W0[c * 144 + 128 + k];
            m0 += peW[2 * k] * w;
            m1 += peW[2 * k + 1] * w;
            be += peB[k] * w;
        }
        g_M0[c] = m0; g_M0[CH + c] = m1;
        g_beff0[c] = be + b0[c];
    }
}

// ---- fused GEMM layer: TM=128, warp M=32, two-phase W buffer ----
__global__ __launch_bounds__(256, 2) void k_gemm(const float* __restrict__ xin,
                                                 const float* __restrict__ bias,
                                                 int layer) {
    extern __shared__ char sm[];
    char* Ahi = sm;              // [128][256B]
    char* Alo = sm + 32768;
    char* Wb  = sm + 65536;      // [128][256B] — Whi then Wlo

    __shared__ float s_B[CH], s_M0x[CH], s_M0y[CH], s_sc[CH], s_sh[CH];
    __shared__ float s_Px[TM], s_Py[TM];

    int tid = threadIdx.x;
    int wid = tid >> 5;
    int lane = tid & 31;
    int nb = blockIdx.x * TM;

    if (tid < CH) {
        s_B[tid] = layer ? bias[tid] : g_beff0[tid];
        s_M0x[tid] = g_M0[tid];
        s_M0y[tid] = g_M0[CH + tid];
        s_sc[tid] = g_scale[0][tid];
        s_sh[tid] = g_shift[0][tid];
    }
    if (tid < TM) {
        int local = (nb + tid) % NPG;
        s_Px[tid] = (float)(local >> 5) * (1.f / 31.f);
        s_Py[tid] = (float)(local & 31) * (1.f / 31.f);
    }
    __syncthreads();

    // ---- load + split A tile: 128 rows x 16 chunks of 8 ch ----
    const float4* src4 = layer ? (const float4*)g_y0 : (const float4*)xin;
#pragma unroll
    for (int i = 0; i < 8; i++) {
        int u = tid + 256 * i;        // 0..2047
        int row = u >> 4;
        int chunk = u & 15;
        int gn = nb + row;
        float v[8];
        if (gn < NODES) {
            float4 p0 = src4[(size_t)gn * 32 + chunk * 2];
            float4 p1 = src4[(size_t)gn * 32 + chunk * 2 + 1];
            v[0] = p0.x; v[1] = p0.y; v[2] = p0.z; v[3] = p0.w;
            v[4] = p1.x; v[5] = p1.y; v[6] = p1.z; v[7] = p1.w;
            if (layer) {
#pragma unroll
                for (int j = 0; j < 8; j++) {
                    int c = chunk * 8 + j;
                    float a = v[j] * s_sc[c] + s_sh[c];
                    v[j] = (a > 0.f) ? a : (expf(a) - 1.f);
                }
            }
        } else {
#pragma unroll
            for (int j = 0; j < 8; j++) v[j] = 0.f;
        }
        uint4 hi, lo;
        hi.x = split_pack_hi(v[0], v[1], lo.x);
        hi.y = split_pack_hi(v[2], v[3], lo.y);
        hi.z = split_pack_hi(v[4], v[5], lo.z);
        hi.w = split_pack_hi(v[6], v[7], lo.w);
        uint32_t off = swz((uint32_t)row, (uint32_t)chunk);
        *(uint4*)(Ahi + off) = hi;
        *(uint4*)(Alo + off) = lo;
    }
    // ---- copy W_hi image ----
    {
        const float4* wh = (const float4*)g_Wimg[layer][0];
#pragma unroll
        for (int i = 0; i < 8; i++) ((float4*)Wb)[tid + 256 * i] = wh[tid + 256 * i];
    }
    __syncthreads();

    // ---- warp tiling: 4 row-groups (32 rows) x 2 ch-halves ----
    int wr = wid >> 1;
    int wc = wid & 1;
    uint32_t la7 = lane & 7;
    uint32_t aSel = (uint32_t)(lane >> 4);
    uint32_t r0base = (uint32_t)(32 * wr + (lane & 15));
    uint32_t bRow = (uint32_t)(64 * wc + (lane & 7) + ((lane >> 4) << 3)) * 256u;
    uint32_t bSel = (uint32_t)((lane >> 3) & 1);
    uint32_t baseAh = smem_u32(Ahi), baseAl = smem_u32(Alo), baseW = smem_u32(Wb);

    float C[2][8][4];
#pragma unroll
    for (int mt = 0; mt < 2; mt++)
#pragma unroll
        for (int n = 0; n < 8; n++)
#pragma unroll
            for (int j = 0; j < 4; j++) C[mt][n][j] = 0.f;

    // ---- phase A: Ahi*Whi + Alo*Whi ----
#pragma unroll
    for (int ks = 0; ks < 8; ks++) {
        uint32_t asw = (((2 * ks + aSel) ^ la7) << 4);
        uint32_t ah[2][4], al[2][4];
#pragma unroll
        for (int mt = 0; mt < 2; mt++) {
            uint32_t ar = (r0base + 16 * mt) * 256u + asw;
            ldsm4(ah[mt][0], ah[mt][1], ah[mt][2], ah[mt][3], baseAh + ar);
            ldsm4(al[mt][0], al[mt][1], al[mt][2], al[mt][3], baseAl + ar);
        }
        uint32_t bsw = (((2 * ks + bSel) ^ la7) << 4);
#pragma unroll
        for (int np = 0; np < 4; np++) {
            uint32_t boff = bRow + np * 4096 + bsw;
            uint32_t w0, w1, w2, w3;
            ldsm4(w0, w1, w2, w3, baseW + boff);
#pragma unroll
            for (int mt = 0; mt < 2; mt++) {
                mma_bf16(C[mt][2 * np],     ah[mt][0], ah[mt][1], ah[mt][2], ah[mt][3], w0, w1);
                mma_bf16(C[mt][2 * np + 1], ah[mt][0], ah[mt][1], ah[mt][2], ah[mt][3], w2, w3);
                mma_bf16(C[mt][2 * np],     al[mt][0], al[mt][1], al[mt][2], al[mt][3], w0, w1);
                mma_bf16(C[mt][2 * np + 1], al[mt][0], al[mt][1], al[mt][2], al[mt][3], w2, w3);
            }
        }
    }
    __syncthreads();

    // ---- swap in W_lo ----
    {
        const float4* wl = (const float4*)g_Wimg[layer][1];
#pragma unroll
        for (int i = 0; i < 8; i++) ((float4*)Wb)[tid + 256 * i] = wl[tid + 256 * i];
    }
    __syncthreads();

    // ---- phase B: Ahi*Wlo ----
#pragma unroll
    for (int ks = 0; ks < 8; ks++) {
        uint32_t asw = (((2 * ks + aSel) ^ la7) << 4);
        uint32_t ah[2][4];
#pragma unroll
        for (int mt = 0; mt < 2; mt++) {
            uint32_t ar = (r0base + 16 * mt) * 256u + asw;
            ldsm4(ah[mt][0], ah[mt][1], ah[mt][2], ah[mt][3], baseAh + ar);
        }
        uint32_t bsw = (((2 * ks + bSel) ^ la7) << 4);
#pragma unroll
        for (int np = 0; np < 4; np++) {
            uint32_t boff = bRow + np * 4096 + bsw;
            uint32_t w0, w1, w2, w3;
            ldsm4(w0, w1, w2, w3, baseW + boff);
#pragma unroll
            for (int mt = 0; mt < 2; mt++) {
                mma_bf16(C[mt][2 * np],     ah[mt][0], ah[mt][1], ah[mt][2], ah[mt][3], w0, w1);
                mma_bf16(C[mt][2 * np + 1], ah[mt][0], ah[mt][1], ah[mt][2], ah[mt][3], w2, w3);
            }
        }
    }
    __syncthreads();

    // ---- stage C to smem ----
    float* stage = (float*)sm;     // [128][132] = 67.5KB, fits in 96KB
    {
        int tr = lane >> 2;
        int tc = (lane & 3) * 2;
#pragma unroll
        for (int mt = 0; mt < 2; mt++) {
            int ra = 32 * wr + 16 * mt + tr, rb = ra + 8;
#pragma unroll
            for (int nt = 0; nt < 8; nt++) {
                int c = 64 * wc + 8 * nt + tc;
                *(float2*)&stage[ra * 132 + c] = make_float2(C[mt][nt][0], C[mt][nt][1]);
                *(float2*)&stage[rb * 132 + c] = make_float2(C[mt][nt][2], C[mt][nt][3]);
            }
        }
    }
    __syncthreads();

    // ---- writeout + BN stats ----
    {
        int c = tid & 127;
        int half = tid >> 7;
        float bc = s_B[c], mx = s_M0x[c], my = s_M0y[c];
        float* dst = layer ? (float*)g_y1 : (float*)g_y0;
        float s = 0.f, q = 0.f;
#pragma unroll 4
        for (int r = half * 64; r < half * 64 + 64; r++) {
            int node = nb + r;
            if (node < NODES) {
                float v = stage[r * 132 + c] + bc;
                if (!layer) v += s_Px[r] * mx + s_Py[r] * my;
                dst[(size_t)node * CH + c] = v;
                s += v;
                q += v * v;
            }
        }
        atomicAdd(&g_sum[layer][c], s);
        atomicAdd(&g_sq[layer][c], q);
    }
}

__global__ void k_bnfin(const float* __restrict__ gam, const float* __restrict__ bet, int layer) {
    int c = threadIdx.x;
    float mu = g_sum[layer][c] * (1.f / NODES);
    float var = g_sq[layer][c] * (1.f / NODES) - mu * mu;
    float sc = gam[c] * rsqrtf(var + 1e-5f);
    g_scale[layer][c] = sc;
    g_shift[layer][c] = bet[c] - mu * sc;
}

__global__ __launch_bounds__(256) void k_pool() {
    int g = blockIdx.x >> 3;
    int sub = blockIdx.x & 7;
    int nstart = g * NPG + sub * 125;
    int c = threadIdx.x & 127;
    int half = threadIdx.x >> 7;
    const float* y1 = (const float*)g_y1;
    float sc = g_scale[1][c], sh = g_shift[1][c];
    float s = 0.f;
    for (int n = nstart + half; n < nstart + 125; n += 2) {
        float v = y1[(size_t)n * CH + c] * sc + sh;
        v = (v > 0.f) ? v : (expf(v) - 1.f);
        s += v;
    }
    __shared__ float red[256];
    red[threadIdx.x] = s;
    __syncthreads();
    if (half == 0) atomicAdd(&g_pool[g * CH + c], red[c] + red[128 + c]);
}

__global__ void k_fc(const float* __restrict__ fcW, const float* __restrict__ fcb,
                     float* __restrict__ out) {
    int g = blockIdx.x;
    int o = threadIdx.x;
    float s = 0.f;
#pragma unroll 8
    for (int c = 0; c < CH; c++) s += g_pool[g * CH + c] * fcW[o * CH + c];
    out[g * OUTD + o] = s * (1.f / NPG) + fcb[o];
}

extern "C" void kernel_launch(void* const* d_in, const int* in_sizes, int n_in,
                              void* d_out, int out_size) {
    const float* x   = (const float*)d_in[0];
    const float* peW = (const float*)d_in[3];
    const float* peB = (const float*)d_in[4];
    const float* W0  = (const float*)d_in[5];
    const float* b0  = (const float*)d_in[8];
    const float* g0  = (const float*)d_in[9];
    const float* bb0 = (const float*)d_in[10];
    const float* W1  = (const float*)d_in[11];
    const float* b1  = (const float*)d_in[14];
    const float* g1  = (const float*)d_in[15];
    const float* bb1 = (const float*)d_in[16];
    const float* fcW = (const float*)d_in[17];
    const float* fcb = (const float*)d_in[18];
    float* out = (float*)d_out;

    static bool once = false;
    if (!once) {
        cudaFuncSetAttribute(k_gemm, cudaFuncAttributeMaxDynamicSharedMemorySize, DSMEM);
        once = true;
    }

    k_prep<<<128, 256>>>(peW, peB, W0, b0, W1);
    k_gemm<<<NBLK, 256, DSMEM>>>(x, b0, 0);
    k_bnfin<<<1, CH>>>(g0, bb0, 0);
    k_gemm<<<NBLK, 256, DSMEM>>>(x, b1, 1);
    k_bnfin<<<1, CH>>>(g1, bb1, 1);
    k_pool<<<GRAPHS * 8, 256>>>();
    k_fc<<<GRAPHS, OUTD>>>(fcW, fcb, out);
}

// round 5
// speedup vs baseline: 2.0681x; 1.1439x over previous
#include <cuda_runtime.h>
#include <cuda_fp16.h>
#include <math.h>
#include <stdint.h>

#define NODES 100000
#define GRAPHS 100
#define NPG 1000
#define CH 128
#define OUTD 64
#define POSD 16
#define TM 128
#define NBLK ((NODES + TM - 1) / TM)
#define DSMEM (128 * 132 * 4)   // stage; mainloop uses 64K of it (A 32K | W 32K)

// ---- device-global scratch ----
__device__ __half g_y0[(size_t)NODES * CH];
__device__ __half g_y1[(size_t)NODES * CH];
__device__ unsigned char g_Wimg[2][32768];  // [layer] pre-swizzled fp16 image
__device__ float g_M0[2 * CH];
__device__ float g_beff0[CH];
__device__ float g_sum[2][CH];
__device__ float g_sq[2][CH];
__device__ float g_scale[2][CH];
__device__ float g_shift[2][CH];
__device__ float g_pool[GRAPHS * CH];

__device__ __forceinline__ uint32_t smem_u32(const void* p) {
    uint32_t a;
    asm("{ .reg .u64 t; cvta.to.shared.u64 t, %1; cvt.u32.u64 %0, t; }" : "=r"(a) : "l"(p));
    return a;
}
__device__ __forceinline__ uint32_t swz(uint32_t row, uint32_t chunk) {
    return row * 256u + ((chunk ^ (row & 7u)) << 4);
}
__device__ __forceinline__ void ldsm4(uint32_t& r0, uint32_t& r1, uint32_t& r2, uint32_t& r3,
                                      uint32_t addr) {
    asm volatile("ldmatrix.sync.aligned.m8n8.x4.shared.b16 {%0,%1,%2,%3}, [%4];"
                 : "=r"(r0), "=r"(r1), "=r"(r2), "=r"(r3) : "r"(addr));
}
__device__ __forceinline__ void mma_f16(float* c, uint32_t a0, uint32_t a1, uint32_t a2,
                                        uint32_t a3, uint32_t b0, uint32_t b1) {
    asm volatile(
        "mma.sync.aligned.m16n8k16.row.col.f32.f16.f16.f32 "
        "{%0,%1,%2,%3}, {%4,%5,%6,%7}, {%8,%9}, {%0,%1,%2,%3};"
        : "+f"(c[0]), "+f"(c[1]), "+f"(c[2]), "+f"(c[3])
        : "r"(a0), "r"(a1), "r"(a2), "r"(a3), "r"(b0), "r"(b1));
}
__device__ __forceinline__ uint32_t h2u(__half2 h) {
    uint32_t u;
    memcpy(&u, &h, 4);
    return u;
}

__global__ void k_prep(const float* __restrict__ peW, const float* __restrict__ peB,
                       const float* __restrict__ W0, const float* __restrict__ b0,
                       const float* __restrict__ W1) {
    int t = blockIdx.x * blockDim.x + threadIdx.x;
    int stride = gridDim.x * blockDim.x;
    for (int i = t; i < GRAPHS * CH; i += stride) g_pool[i] = 0.f;
    for (int i = t; i < CH; i += stride) {
        g_sum[0][i] = 0.f; g_sum[1][i] = 0.f;
        g_sq[0][i] = 0.f;  g_sq[1][i] = 0.f;
    }
    for (int i = t; i < 2 * CH * CH; i += stride) {
        int layer = i >> 14, e = i & 16383, c = e >> 7, k = e & 127;
        float w = layer ? W1[c * CH + k] : W0[c * 144 + k];
        uint32_t off = swz((uint32_t)c, (uint32_t)(k >> 3)) + (k & 7) * 2;
        *(__half*)(g_Wimg[layer] + off) = __float2half_rn(w);
    }
    if (blockIdx.x == 0 && threadIdx.x < CH) {
        int c = threadIdx.x;
        float m0 = 0.f, m1 = 0.f, be = 0.f;
        for (int k = 0; k < POSD; k++) {
            float w = W0[c * 144 + 128 + k];
            m0 += peW[2 * k] * w;
            m1 += peW[2 * k + 1] * w;
            be += peB[k] * w;
        }
        g_M0[c] = m0; g_M0[CH + c] = m1;
        g_beff0[c] = be + b0[c];
    }
}

// ---- fused GEMM layer: single fp16 product, TM=128, warp tile 32x64 ----
__global__ __launch_bounds__(256, 2) void k_gemm(const float* __restrict__ xin,
                                                 const float* __restrict__ bias,
                                                 int layer) {
    extern __shared__ char sm[];
    char* At = sm;               // [128][256B] fp16 A tile (swizzled)
    char* Wt = sm + 32768;       // [128][256B] fp16 W tile (swizzled)

    __shared__ float s_B[CH], s_M0x[CH], s_M0y[CH], s_sc[CH], s_sh[CH];
    __shared__ float s_Px[TM], s_Py[TM];

    int tid = threadIdx.x;
    int wid = tid >> 5;
    int lane = tid & 31;
    int nb = blockIdx.x * TM;

    if (tid < CH) {
        s_B[tid] = layer ? bias[tid] : g_beff0[tid];
        s_M0x[tid] = g_M0[tid];
        s_M0y[tid] = g_M0[CH + tid];
        s_sc[tid] = g_scale[0][tid];
        s_sh[tid] = g_shift[0][tid];
    }
    if (tid < TM) {
        int local = (nb + tid) % NPG;
        s_Px[tid] = (float)(local >> 5) * (1.f / 31.f);
        s_Py[tid] = (float)(local & 31) * (1.f / 31.f);
    }
    __syncthreads();

    // ---- load + convert A tile: 128 rows x 16 chunks of 8 ch ----
#pragma unroll
    for (int i = 0; i < 8; i++) {
        int u = tid + 256 * i;        // 0..2047
        int row = u >> 4;
        int chunk = u & 15;
        int gn = nb + row;
        uint4 packed = make_uint4(0, 0, 0, 0);
        if (gn < NODES) {
            if (!layer) {
                const float4* src4 = (const float4*)xin;
                float4 p0 = src4[(size_t)gn * 32 + chunk * 2];
                float4 p1 = src4[(size_t)gn * 32 + chunk * 2 + 1];
                packed.x = h2u(__floats2half2_rn(p0.x, p0.y));
                packed.y = h2u(__floats2half2_rn(p0.z, p0.w));
                packed.z = h2u(__floats2half2_rn(p1.x, p1.y));
                packed.w = h2u(__floats2half2_rn(p1.z, p1.w));
            } else {
                uint4 raw = *(const uint4*)&g_y0[(size_t)gn * CH + chunk * 8];
                uint32_t rr[4] = {raw.x, raw.y, raw.z, raw.w};
                uint32_t oo[4];
#pragma unroll
                for (int j = 0; j < 4; j++) {
                    __half2 h;
                    memcpy(&h, &rr[j], 4);
                    float2 f = __half22float2(h);
                    int c = chunk * 8 + 2 * j;
                    float a0 = f.x * s_sc[c] + s_sh[c];
                    float a1 = f.y * s_sc[c + 1] + s_sh[c + 1];
                    a0 = (a0 > 0.f) ? a0 : (expf(a0) - 1.f);
                    a1 = (a1 > 0.f) ? a1 : (expf(a1) - 1.f);
                    oo[j] = h2u(__floats2half2_rn(a0, a1));
                }
                packed = make_uint4(oo[0], oo[1], oo[2], oo[3]);
            }
        }
        *(uint4*)(At + swz((uint32_t)row, (uint32_t)chunk)) = packed;
    }
    // ---- copy W image ----
    {
        const float4* w4 = (const float4*)g_Wimg[layer];
#pragma unroll
        for (int i = 0; i < 8; i++) ((float4*)Wt)[tid + 256 * i] = w4[tid + 256 * i];
    }
    __syncthreads();

    // ---- mainloop: warp tile M=32, N=64 ----
    int wr = wid >> 1;
    int wc = wid & 1;
    uint32_t la7 = lane & 7;
    uint32_t aSel = (uint32_t)(lane >> 4);
    uint32_t r0base = (uint32_t)(32 * wr + (lane & 15));
    uint32_t bRow = (uint32_t)(64 * wc + (lane & 7) + ((lane >> 4) << 3)) * 256u;
    uint32_t bSel = (uint32_t)((lane >> 3) & 1);
    uint32_t baseA = smem_u32(At), baseW = smem_u32(Wt);

    float C[2][8][4];
#pragma unroll
    for (int mt = 0; mt < 2; mt++)
#pragma unroll
        for (int n = 0; n < 8; n++)
#pragma unroll
            for (int j = 0; j < 4; j++) C[mt][n][j] = 0.f;

#pragma unroll
    for (int ks = 0; ks < 8; ks++) {
        uint32_t asw = (((2 * ks + aSel) ^ la7) << 4);
        uint32_t ah[2][4];
#pragma unroll
        for (int mt = 0; mt < 2; mt++) {
            uint32_t ar = (r0base + 16 * mt) * 256u + asw;
            ldsm4(ah[mt][0], ah[mt][1], ah[mt][2], ah[mt][3], baseA + ar);
        }
        uint32_t bsw = (((2 * ks + bSel) ^ la7) << 4);
#pragma unroll
        for (int np = 0; np < 4; np++) {
            uint32_t boff = bRow + np * 4096 + bsw;
            uint32_t w0, w1, w2, w3;
            ldsm4(w0, w1, w2, w3, baseW + boff);
#pragma unroll
            for (int mt = 0; mt < 2; mt++) {
                mma_f16(C[mt][2 * np],     ah[mt][0], ah[mt][1], ah[mt][2], ah[mt][3], w0, w1);
                mma_f16(C[mt][2 * np + 1], ah[mt][0], ah[mt][1], ah[mt][2], ah[mt][3], w2, w3);
            }
        }
    }
    __syncthreads();

    // ---- stage C to smem ----
    float* stage = (float*)sm;     // [128][132]
    {
        int tr = lane >> 2;
        int tc = (lane & 3) * 2;
#pragma unroll
        for (int mt = 0; mt < 2; mt++) {
            int ra = 32 * wr + 16 * mt + tr, rb = ra + 8;
#pragma unroll
            for (int nt = 0; nt < 8; nt++) {
                int c = 64 * wc + 8 * nt + tc;
                *(float2*)&stage[ra * 132 + c] = make_float2(C[mt][nt][0], C[mt][nt][1]);
                *(float2*)&stage[rb * 132 + c] = make_float2(C[mt][nt][2], C[mt][nt][3]);
            }
        }
    }
    __syncthreads();

    // ---- writeout (half2) + BN stats ----
    {
        int c = (tid & 63) * 2;        // channel pair
        int grp = tid >> 6;            // 4 groups of 32 rows
        float b0c = s_B[c], b1c = s_B[c + 1];
        float mx0 = s_M0x[c], my0 = s_M0y[c], mx1 = s_M0x[c + 1], my1 = s_M0y[c + 1];
        __half* dst = layer ? g_y1 : g_y0;
        float s0 = 0.f, q0 = 0.f, s1 = 0.f, q1 = 0.f;
#pragma unroll 4
        for (int r = grp * 32; r < grp * 32 + 32; r++) {
            int node = nb + r;
            if (node < NODES) {
                float v0 = stage[r * 132 + c] + b0c;
                float v1 = stage[r * 132 + c + 1] + b1c;
                if (!layer) {
                    v0 += s_Px[r] * mx0 + s_Py[r] * my0;
                    v1 += s_Px[r] * mx1 + s_Py[r] * my1;
                }
                *(__half2*)&dst[(size_t)node * CH + c] = __floats2half2_rn(v0, v1);
                s0 += v0; q0 += v0 * v0;
                s1 += v1; q1 += v1 * v1;
            }
        }
        atomicAdd(&g_sum[layer][c], s0);
        atomicAdd(&g_sq[layer][c], q0);
        atomicAdd(&g_sum[layer][c + 1], s1);
        atomicAdd(&g_sq[layer][c + 1], q1);
    }
}

__global__ void k_bnfin(const float* __restrict__ gam, const float* __restrict__ bet, int layer) {
    int c = threadIdx.x;
    float mu = g_sum[layer][c] * (1.f / NODES);
    float var = g_sq[layer][c] * (1.f / NODES) - mu * mu;
    float sc = gam[c] * rsqrtf(var + 1e-5f);
    g_scale[layer][c] = sc;
    g_shift[layer][c] = bet[c] - mu * sc;
}

__global__ __launch_bounds__(256) void k_pool() {
    int g = blockIdx.x >> 3;
    int sub = blockIdx.x & 7;
    int nstart = g * NPG + sub * 125;
    int c = threadIdx.x & 127;
    int half = threadIdx.x >> 7;
    float sc = g_scale[1][c], sh = g_shift[1][c];
    float s = 0.f;
    for (int n = nstart + half; n < nstart + 125; n += 2) {
        float v = __half2float(g_y1[(size_t)n * CH + c]) * sc + sh;
        v = (v > 0.f) ? v : (expf(v) - 1.f);
        s += v;
    }
    __shared__ float red[256];
    red[threadIdx.x] = s;
    __syncthreads();
    if (half == 0) atomicAdd(&g_pool[g * CH + c], red[c] + red[128 + c]);
}

__global__ void k_fc(const float* __restrict__ fcW, const float* __restrict__ fcb,
                     float* __restrict__ out) {
    int g = blockIdx.x;
    int o = threadIdx.x;
    float s = 0.f;
#pragma unroll 8
    for (int c = 0; c < CH; c++) s += g_pool[g * CH + c] * fcW[o * CH + c];
    out[g * OUTD + o] = s * (1.f / NPG) + fcb[o];
}

extern "C" void kernel_launch(void* const* d_in, const int* in_sizes, int n_in,
                              void* d_out, int out_size) {
    const float* x   = (const float*)d_in[0];
    const float* peW = (const float*)d_in[3];
    const float* peB = (const float*)d_in[4];
    const float* W0  = (const float*)d_in[5];
    const float* b0  = (const float*)d_in[8];
    const float* g0  = (const float*)d_in[9];
    const float* bb0 = (const float*)d_in[10];
    const float* W1  = (const float*)d_in[11];
    const float* b1  = (const float*)d_in[14];
    const float* g1  = (const float*)d_in[15];
    const float* bb1 = (const float*)d_in[16];
    const float* fcW = (const float*)d_in[17];
    const float* fcb = (const float*)d_in[18];
    float* out = (float*)d_out;

    static bool once = false;
    if (!once) {
        cudaFuncSetAttribute(k_gemm, cudaFuncAttributeMaxDynamicSharedMemorySize, DSMEM);
        once = true;
    }

    k_prep<<<128, 256>>>(peW, peB, W0, b0, W1);
    k_gemm<<<NBLK, 256, DSMEM>>>(x, b0, 0);
    k_bnfin<<<1, CH>>>(g0, bb0, 0);
    k_gemm<<<NBLK, 256, DSMEM>>>(x, b1, 1);
    k_bnfin<<<1, CH>>>(g1, bb1, 1);
    k_pool<<<GRAPHS * 8, 256>>>();
    k_fc<<<GRAPHS, OUTD>>>(fcW, fcb, out);
}

// round 6
// speedup vs baseline: 2.6916x; 1.3015x over previous
#include <cuda_runtime.h>
#include <cuda_fp16.h>
#include <math.h>
#include <stdint.h>

#define NODES 100000
#define GRAPHS 100
#define NPG 1000
#define CH 128
#define OUTD 64
#define POSD 16
#define TM 64
#define NBLK ((NODES + TM - 1) / TM)
#define DSMEM 49152   // A 16K | W 32K ; epilogue reuses as stage(33.8K)+red(4K)

// ---- device-global scratch ----
__device__ __half g_y0[(size_t)NODES * CH];
__device__ __half g_y1[(size_t)NODES * CH];
__device__ unsigned char g_Wimg[2][32768];  // [layer] pre-swizzled fp16 image
__device__ float g_M0[2 * CH];
__device__ float g_beff0[CH];
__device__ float g_sum[2][CH];
__device__ float g_sq[2][CH];
__device__ float g_scale[2][CH];
__device__ float g_shift[2][CH];
__device__ float g_pool[GRAPHS * CH];

__device__ __forceinline__ uint32_t smem_u32(const void* p) {
    uint32_t a;
    asm("{ .reg .u64 t; cvta.to.shared.u64 t, %1; cvt.u32.u64 %0, t; }" : "=r"(a) : "l"(p));
    return a;
}
__device__ __forceinline__ uint32_t swz(uint32_t row, uint32_t chunk) {
    return row * 256u + ((chunk ^ (row & 7u)) << 4);
}
__device__ __forceinline__ void ldsm4(uint32_t& r0, uint32_t& r1, uint32_t& r2, uint32_t& r3,
                                      uint32_t addr) {
    asm volatile("ldmatrix.sync.aligned.m8n8.x4.shared.b16 {%0,%1,%2,%3}, [%4];"
                 : "=r"(r0), "=r"(r1), "=r"(r2), "=r"(r3) : "r"(addr));
}
__device__ __forceinline__ void mma_f16(float* c, uint32_t a0, uint32_t a1, uint32_t a2,
                                        uint32_t a3, uint32_t b0, uint32_t b1) {
    asm volatile(
        "mma.sync.aligned.m16n8k16.row.col.f32.f16.f16.f32 "
        "{%0,%1,%2,%3}, {%4,%5,%6,%7}, {%8,%9}, {%0,%1,%2,%3};"
        : "+f"(c[0]), "+f"(c[1]), "+f"(c[2]), "+f"(c[3])
        : "r"(a0), "r"(a1), "r"(a2), "r"(a3), "r"(b0), "r"(b1));
}
__device__ __forceinline__ uint32_t h2u(__half2 h) {
    uint32_t u;
    memcpy(&u, &h, 4);
    return u;
}

__global__ void k_prep(const float* __restrict__ peW, const float* __restrict__ peB,
                       const float* __restrict__ W0, const float* __restrict__ b0,
                       const float* __restrict__ W1) {
    int t = blockIdx.x * blockDim.x + threadIdx.x;
    int stride = gridDim.x * blockDim.x;
    for (int i = t; i < GRAPHS * CH; i += stride) g_pool[i] = 0.f;
    for (int i = t; i < CH; i += stride) {
        g_sum[0][i] = 0.f; g_sum[1][i] = 0.f;
        g_sq[0][i] = 0.f;  g_sq[1][i] = 0.f;
    }
    for (int i = t; i < 2 * CH * CH; i += stride) {
        int layer = i >> 14, e = i & 16383, c = e >> 7, k = e & 127;
        float w = layer ? W1[c * CH + k] : W0[c * 144 + k];
        uint32_t off = swz((uint32_t)c, (uint32_t)(k >> 3)) + (k & 7) * 2;
        *(__half*)(g_Wimg[layer] + off) = __float2half_rn(w);
    }
    if (blockIdx.x == 0 && threadIdx.x < CH) {
        int c = threadIdx.x;
        float m0 = 0.f, m1 = 0.f, be = 0.f;
        for (int k = 0; k < POSD; k++) {
            float w = W0[c * 144 + 128 + k];
            m0 += peW[2 * k] * w;
            m1 += peW[2 * k + 1] * w;
            be += peB[k] * w;
        }
        g_M0[c] = m0; g_M0[CH + c] = m1;
        g_beff0[c] = be + b0[c];
    }
}

// ---- fused GEMM layer: TM=64, warp tile 32x32, 4 CTAs/SM ----
__global__ __launch_bounds__(256, 4) void k_gemm(const float* __restrict__ xin,
                                                 const float* __restrict__ bias,
                                                 int layer) {
    extern __shared__ char sm[];
    char* At = sm;               // [64][256B] fp16 A tile (swizzled)
    char* Wt = sm + 16384;       // [128][256B] fp16 W tile (swizzled)

    __shared__ float s_B[CH], s_M0x[CH], s_M0y[CH], s_sc[CH], s_sh[CH];
    __shared__ float s_Px[TM], s_Py[TM];

    int tid = threadIdx.x;
    int wid = tid >> 5;
    int lane = tid & 31;
    int nb = blockIdx.x * TM;

    if (tid < CH) {
        s_B[tid] = layer ? bias[tid] : g_beff0[tid];
        s_M0x[tid] = g_M0[tid];
        s_M0y[tid] = g_M0[CH + tid];
        s_sc[tid] = g_scale[0][tid];
        s_sh[tid] = g_shift[0][tid];
    }
    if (tid < TM) {
        int local = (nb + tid) % NPG;
        s_Px[tid] = (float)(local >> 5) * (1.f / 31.f);
        s_Py[tid] = (float)(local & 31) * (1.f / 31.f);
    }
    __syncthreads();

    // ---- load + convert A tile: 64 rows x 16 chunks of 8 ch ----
#pragma unroll
    for (int i = 0; i < 4; i++) {
        int u = tid + 256 * i;        // 0..1023
        int row = u >> 4;
        int chunk = u & 15;
        int gn = nb + row;
        uint4 packed = make_uint4(0, 0, 0, 0);
        if (gn < NODES) {
            if (!layer) {
                const float4* src4 = (const float4*)xin;
                float4 p0 = src4[(size_t)gn * 32 + chunk * 2];
                float4 p1 = src4[(size_t)gn * 32 + chunk * 2 + 1];
                packed.x = h2u(__floats2half2_rn(p0.x, p0.y));
                packed.y = h2u(__floats2half2_rn(p0.z, p0.w));
                packed.z = h2u(__floats2half2_rn(p1.x, p1.y));
                packed.w = h2u(__floats2half2_rn(p1.z, p1.w));
            } else {
                uint4 raw = *(const uint4*)&g_y0[(size_t)gn * CH + chunk * 8];
                uint32_t rr[4] = {raw.x, raw.y, raw.z, raw.w};
                uint32_t oo[4];
#pragma unroll
                for (int j = 0; j < 4; j++) {
                    __half2 h;
                    memcpy(&h, &rr[j], 4);
                    float2 f = __half22float2(h);
                    int c = chunk * 8 + 2 * j;
                    float a0 = f.x * s_sc[c] + s_sh[c];
                    float a1 = f.y * s_sc[c + 1] + s_sh[c + 1];
                    a0 = (a0 > 0.f) ? a0 : (expf(a0) - 1.f);
                    a1 = (a1 > 0.f) ? a1 : (expf(a1) - 1.f);
                    oo[j] = h2u(__floats2half2_rn(a0, a1));
                }
                packed = make_uint4(oo[0], oo[1], oo[2], oo[3]);
            }
        }
        *(uint4*)(At + swz((uint32_t)row, (uint32_t)chunk)) = packed;
    }
    // ---- copy W image (32KB) ----
    {
        const float4* w4 = (const float4*)g_Wimg[layer];
#pragma unroll
        for (int i = 0; i < 8; i++) ((float4*)Wt)[tid + 256 * i] = w4[tid + 256 * i];
    }
    __syncthreads();

    // ---- mainloop: warp tile M=32 (wr), N=32 (wc) ----
    int wr = wid >> 2;          // 0..1
    int wc = wid & 3;           // 0..3
    uint32_t la7 = lane & 7;
    uint32_t aSel = (uint32_t)(lane >> 4);
    uint32_t r0base = (uint32_t)(32 * wr + (lane & 15));
    uint32_t bRow = (uint32_t)(32 * wc + (lane & 7) + ((lane >> 4) << 3)) * 256u;
    uint32_t bSel = (uint32_t)((lane >> 3) & 1);
    uint32_t baseA = smem_u32(At), baseW = smem_u32(Wt);

    float C[2][4][4];
#pragma unroll
    for (int mt = 0; mt < 2; mt++)
#pragma unroll
        for (int n = 0; n < 4; n++)
#pragma unroll
            for (int j = 0; j < 4; j++) C[mt][n][j] = 0.f;

#pragma unroll
    for (int ks = 0; ks < 8; ks++) {
        uint32_t asw = (((2 * ks + aSel) ^ la7) << 4);
        uint32_t ah[2][4];
#pragma unroll
        for (int mt = 0; mt < 2; mt++) {
            uint32_t ar = (r0base + 16 * mt) * 256u + asw;
            ldsm4(ah[mt][0], ah[mt][1], ah[mt][2], ah[mt][3], baseA + ar);
        }
        uint32_t bsw = (((2 * ks + bSel) ^ la7) << 4);
#pragma unroll
        for (int np = 0; np < 2; np++) {
            uint32_t boff = bRow + np * 4096 + bsw;
            uint32_t w0, w1, w2, w3;
            ldsm4(w0, w1, w2, w3, baseW + boff);
#pragma unroll
            for (int mt = 0; mt < 2; mt++) {
                mma_f16(C[mt][2 * np],     ah[mt][0], ah[mt][1], ah[mt][2], ah[mt][3], w0, w1);
                mma_f16(C[mt][2 * np + 1], ah[mt][0], ah[mt][1], ah[mt][2], ah[mt][3], w2, w3);
            }
        }
    }
    __syncthreads();

    // ---- stage C to smem (reuse A|W region) ----
    float* stage = (float*)sm;       // [64][132] = 33792B
    float4* red4 = (float4*)(sm + 33792);  // [256]
    {
        int tr = lane >> 2;
        int tc = (lane & 3) * 2;
#pragma unroll
        for (int mt = 0; mt < 2; mt++) {
            int ra = 32 * wr + 16 * mt + tr, rb = ra + 8;
#pragma unroll
            for (int nt = 0; nt < 4; nt++) {
                int c = 32 * wc + 8 * nt + tc;
                *(float2*)&stage[ra * 132 + c] = make_float2(C[mt][nt][0], C[mt][nt][1]);
                *(float2*)&stage[rb * 132 + c] = make_float2(C[mt][nt][2], C[mt][nt][3]);
            }
        }
    }
    __syncthreads();

    // ---- writeout (half2) + BN stat partials ----
    {
        int c = (tid & 63) * 2;
        int grp = tid >> 6;            // 4 groups x 16 rows
        float b0c = s_B[c], b1c = s_B[c + 1];
        float mx0 = s_M0x[c], my0 = s_M0y[c], mx1 = s_M0x[c + 1], my1 = s_M0y[c + 1];
        __half* dst = layer ? g_y1 : g_y0;
        float s0 = 0.f, q0 = 0.f, s1 = 0.f, q1 = 0.f;
#pragma unroll 4
        for (int r = grp * 16; r < grp * 16 + 16; r++) {
            int node = nb + r;
            if (node < NODES) {
                float v0 = stage[r * 132 + c] + b0c;
                float v1 = stage[r * 132 + c + 1] + b1c;
                if (!layer) {
                    v0 += s_Px[r] * mx0 + s_Py[r] * my0;
                    v1 += s_Px[r] * mx1 + s_Py[r] * my1;
                }
                *(__half2*)&dst[(size_t)node * CH + c] = __floats2half2_rn(v0, v1);
                s0 += v0; q0 += v0 * v0;
                s1 += v1; q1 += v1 * v1;
            }
        }
        red4[tid] = make_float4(s0, q0, s1, q1);
    }
    __syncthreads();
    if (tid < 64) {
        float4 a = red4[tid], b = red4[tid + 64], cc = red4[tid + 128], d = red4[tid + 192];
        int c = tid * 2;
        atomicAdd(&g_sum[layer][c],     a.x + b.x + cc.x + d.x);
        atomicAdd(&g_sq[layer][c],      a.y + b.y + cc.y + d.y);
        atomicAdd(&g_sum[layer][c + 1], a.z + b.z + cc.z + d.z);
        atomicAdd(&g_sq[layer][c + 1],  a.w + b.w + cc.w + d.w);
    }
}

__global__ void k_bnfin(const float* __restrict__ gam, const float* __restrict__ bet, int layer) {
    int c = threadIdx.x;
    float mu = g_sum[layer][c] * (1.f / NODES);
    float var = g_sq[layer][c] * (1.f / NODES) - mu * mu;
    float sc = gam[c] * rsqrtf(var + 1e-5f);
    g_scale[layer][c] = sc;
    g_shift[layer][c] = bet[c] - mu * sc;
}

__global__ __launch_bounds__(256) void k_pool() {
    int g = blockIdx.x >> 3;
    int sub = blockIdx.x & 7;
    int nstart = g * NPG + sub * 125;
    int c = threadIdx.x & 127;
    int half = threadIdx.x >> 7;
    float sc = g_scale[1][c], sh = g_shift[1][c];
    float s = 0.f;
    for (int n = nstart + half; n < nstart + 125; n += 2) {
        float v = __half2float(g_y1[(size_t)n * CH + c]) * sc + sh;
        v = (v > 0.f) ? v : (expf(v) - 1.f);
        s += v;
    }
    __shared__ float red[256];
    red[threadIdx.x] = s;
    __syncthreads();
    if (half == 0) atomicAdd(&g_pool[g * CH + c], red[c] + red[128 + c]);
}

__global__ void k_fc(const float* __restrict__ fcW, const float* __restrict__ fcb,
                     float* __restrict__ out) {
    int g = blockIdx.x;
    int o = threadIdx.x;
    float s = 0.f;
#pragma unroll 8
    for (int c = 0; c < CH; c++) s += g_pool[g * CH + c] * fcW[o * CH + c];
    out[g * OUTD + o] = s * (1.f / NPG) + fcb[o];
}

extern "C" void kernel_launch(void* const* d_in, const int* in_sizes, int n_in,
                              void* d_out, int out_size) {
    const float* x   = (const float*)d_in[0];
    const float* peW = (const float*)d_in[3];
    const float* peB = (const float*)d_in[4];
    const float* W0  = (const float*)d_in[5];
    const float* b0  = (const float*)d_in[8];
    const float* g0  = (const float*)d_in[9];
    const float* bb0 = (const float*)d_in[10];
    const float* W1  = (const float*)d_in[11];
    const float* b1  = (const float*)d_in[14];
    const float* g1  = (const float*)d_in[15];
    const float* bb1 = (const float*)d_in[16];
    const float* fcW = (const float*)d_in[17];
    const float* fcb = (const float*)d_in[18];
    float* out = (float*)d_out;

    static bool once = false;
    if (!once) {
        cudaFuncSetAttribute(k_gemm, cudaFuncAttributeMaxDynamicSharedMemorySize, DSMEM);
        once = true;
    }

    k_prep<<<128, 256>>>(peW, peB, W0, b0, W1);
    k_gemm<<<NBLK, 256, DSMEM>>>(x, b0, 0);
    k_bnfin<<<1, CH>>>(g0, bb0, 0);
    k_gemm<<<NBLK, 256, DSMEM>>>(x, b1, 1);
    k_bnfin<<<1, CH>>>(g1, bb1, 1);
    k_pool<<<GRAPHS * 8, 256>>>();
    k_fc<<<GRAPHS, OUTD>>>(fcW, fcb, out);
}